// round 1
// baseline (speedup 1.0000x reference)
#include <cuda_runtime.h>

#define BATCH 8
#define CH 3
#define H 1024
#define W 1280
#define HW (H * W)
#define NPIX (BATCH * HW)
#define EPS 1e-7f
#define MIN_DEPTH 10.0f
#define MAX_DEPTH 255.0f

// Per-batch fused parameters: M (9 floats, row-major 3x3) + c (3 floats)
__device__ float g_MC[BATCH * 12];

__global__ void setup_params_kernel(const float* __restrict__ srcK,
                                    const float* __restrict__ tgtK,
                                    const float* __restrict__ tvec) {
    int b = threadIdx.x;
    if (b >= BATCH) return;
    const float* S = srcK + b * 16;   // 4x4 row-major
    const float* T = tgtK + b * 16;
    const float* t = tvec + b * 3;

    // inverse of source_K[:3,:3]
    float a00 = S[0], a01 = S[1], a02 = S[2];
    float a10 = S[4], a11 = S[5], a12 = S[6];
    float a20 = S[8], a21 = S[9], a22 = S[10];
    float det = a00 * (a11 * a22 - a12 * a21)
              - a01 * (a10 * a22 - a12 * a20)
              + a02 * (a10 * a21 - a11 * a20);
    float id = 1.0f / det;
    float i00 = (a11 * a22 - a12 * a21) * id;
    float i01 = (a02 * a21 - a01 * a22) * id;
    float i02 = (a01 * a12 - a02 * a11) * id;
    float i10 = (a12 * a20 - a10 * a22) * id;
    float i11 = (a00 * a22 - a02 * a20) * id;
    float i12 = (a02 * a10 - a00 * a12) * id;
    float i20 = (a10 * a21 - a11 * a20) * id;
    float i21 = (a01 * a20 - a00 * a21) * id;
    float i22 = (a00 * a11 - a01 * a10) * id;

    // K_t[:3,:3]
    float k00 = T[0], k01 = T[1], k02 = T[2];
    float k10 = T[4], k11 = T[5], k12 = T[6];
    float k20 = T[8], k21 = T[9], k22 = T[10];

    float* P = g_MC + b * 12;
    // M = K_t3 * invS
    P[0] = k00 * i00 + k01 * i10 + k02 * i20;
    P[1] = k00 * i01 + k01 * i11 + k02 * i21;
    P[2] = k00 * i02 + k01 * i12 + k02 * i22;
    P[3] = k10 * i00 + k11 * i10 + k12 * i20;
    P[4] = k10 * i01 + k11 * i11 + k12 * i21;
    P[5] = k10 * i02 + k11 * i12 + k12 * i22;
    P[6] = k20 * i00 + k21 * i10 + k22 * i20;
    P[7] = k20 * i01 + k21 * i11 + k22 * i21;
    P[8] = k20 * i02 + k21 * i12 + k22 * i22;
    // c = K_t3 * t
    P[9]  = k00 * t[0] + k01 * t[1] + k02 * t[2];
    P[10] = k10 * t[0] + k11 * t[1] + k12 * t[2];
    P[11] = k20 * t[0] + k21 * t[1] + k22 * t[2];
}

__global__ __launch_bounds__(256) void synth_kernel(const float* __restrict__ img,
                                                    const float* __restrict__ disp,
                                                    float* __restrict__ out) {
    int tid = blockIdx.x * blockDim.x + threadIdx.x;
    if (tid >= NPIX) return;
    int b = tid / HW;
    int rem = tid - b * HW;
    int y = rem / W;
    int x = rem - y * W;

    const float* P = g_MC + b * 12;
    float m0 = P[0], m1 = P[1], m2 = P[2];
    float m3 = P[3], m4 = P[4], m5 = P[5];
    float m6 = P[6], m7 = P[7], m8 = P[8];
    float c0 = P[9], c1 = P[10], c2 = P[11];

    // disp -> depth
    float d = disp[tid];
    const float min_disp = 1.0f / MAX_DEPTH;
    const float max_disp = 1.0f / MIN_DEPTH;
    float scaled = min_disp + (max_disp - min_disp) * d;
    float depth = 1.0f / scaled;

    float fx = (float)x, fy = (float)y;
    float cpx = depth * (m0 * fx + m1 * fy + m2) + c0;
    float cpy = depth * (m3 * fx + m4 * fy + m5) + c1;
    float cpz = depth * (m6 * fx + m7 * fy + m8) + c2;

    float inv_z = 1.0f / (cpz + EPS);
    float pcx = cpx * inv_z;
    float pcy = cpy * inv_z;

    // grid in [-1,1], then to sample space (align_corners=False)
    float gx = (pcx * (1.0f / (float)(W - 1)) - 0.5f) * 2.0f;
    float gy = (pcy * (1.0f / (float)(H - 1)) - 0.5f) * 2.0f;
    float xf = (gx + 1.0f) * (float)W * 0.5f - 0.5f;
    float yf = (gy + 1.0f) * (float)H * 0.5f - 0.5f;

    float x0f = floorf(xf);
    float y0f = floorf(yf);
    float wx = xf - x0f;
    float wy = yf - y0f;

    int x0 = (int)x0f;
    int y0 = (int)y0f;
    int x1 = min(max(x0 + 1, 0), W - 1);
    int y1 = min(max(y0 + 1, 0), H - 1);
    x0 = min(max(x0, 0), W - 1);
    y0 = min(max(y0, 0), H - 1);

    float w00 = (1.0f - wx) * (1.0f - wy);
    float w01 = wx * (1.0f - wy);
    float w10 = (1.0f - wx) * wy;
    float w11 = wx * wy;

    const float* imb = img + (size_t)b * CH * HW;
    float* outb = out + (size_t)b * CH * HW;
    int o00 = y0 * W + x0;
    int o01 = y0 * W + x1;
    int o10 = y1 * W + x0;
    int o11 = y1 * W + x1;
    int opix = y * W + x;

#pragma unroll
    for (int ch = 0; ch < CH; ch++) {
        const float* p = imb + ch * HW;
        float v = __ldg(p + o00) * w00 + __ldg(p + o01) * w01
                + __ldg(p + o10) * w10 + __ldg(p + o11) * w11;
        outb[ch * HW + opix] = v;
    }
}

extern "C" void kernel_launch(void* const* d_in, const int* in_sizes, int n_in,
                              void* d_out, int out_size) {
    const float* img  = (const float*)d_in[0];
    const float* disp = (const float*)d_in[1];
    const float* srcK = (const float*)d_in[2];
    const float* tgtK = (const float*)d_in[3];
    const float* tvec = (const float*)d_in[4];
    float* out = (float*)d_out;

    setup_params_kernel<<<1, BATCH>>>(srcK, tgtK, tvec);
    synth_kernel<<<(NPIX + 255) / 256, 256>>>(img, disp, out);
}